// round 10
// baseline (speedup 1.0000x reference)
#include <cuda_runtime.h>
#include <cuda_bf16.h>
#include <cstdint>

#define EPS_EYE 1e-07f
#define BLK 128
#define TILE (BLK * 2)                 // 256 points per tile (2 per thread)
#define PTS_PER_BLK (TILE * 2)         // 512
#define TILE_BYTES (TILE * 9 * 4)      // 9216

__device__ __forceinline__ uint32_t smem_u32(const void* p) {
    uint32_t a;
    asm("{ .reg .u64 t; cvta.to.shared.u64 t, %1; cvt.u32.u64 %0, t; }"
        : "=r"(a) : "l"(p));
    return a;
}

__device__ __forceinline__ void compute_cov(float sx, float sy, float sz,
                                            float4 q, float* __restrict__ o)
{
    float ex = __expf(sx), ey = __expf(sy), ez = __expf(sz);
    float a = ex * ex, b = ey * ey, c = ez * ez;

    float x = q.x, y = q.y, z = q.z, w = q.w;
    float inv = rsqrtf(x * x + y * y + z * z + w * w);
    x *= inv; y *= inv; z *= inv; w *= inv;

    float xx = x * x, yy = y * y, zz = z * z;
    float xy = x * y, xz = x * z, yz = y * z;
    float wx = w * x, wy = w * y, wz = w * z;

    float r00 = 1.f - 2.f * (yy + zz);
    float r01 = 2.f * (xy - wz);
    float r02 = 2.f * (xz + wy);
    float r10 = 2.f * (xy + wz);
    float r11 = 1.f - 2.f * (xx + zz);
    float r12 = 2.f * (yz - wx);
    float r20 = 2.f * (xz - wy);
    float r21 = 2.f * (yz + wx);
    float r22 = 1.f - 2.f * (xx + yy);

    float c00 = r00 * r00 * a + r01 * r01 * b + r02 * r02 * c + EPS_EYE;
    float c01 = r00 * r10 * a + r01 * r11 * b + r02 * r12 * c;
    float c02 = r00 * r20 * a + r01 * r21 * b + r02 * r22 * c;
    float c11 = r10 * r10 * a + r11 * r11 * b + r12 * r12 * c + EPS_EYE;
    float c12 = r10 * r20 * a + r11 * r21 * b + r12 * r22 * c;
    float c22 = r20 * r20 * a + r21 * r21 * b + r22 * r22 * c + EPS_EYE;

    o[0] = c00; o[1] = c01; o[2] = c02;
    o[3] = c01; o[4] = c11; o[5] = c12;
    o[6] = c02; o[7] = c12; o[8] = c22;
}

__device__ __forceinline__ void issue_tma_store(const float* gdst, const float* sbuf)
{
    asm volatile("fence.proxy.async.shared::cta;" ::: "memory");
    uint32_t saddr = smem_u32(sbuf);
    asm volatile(
        "cp.async.bulk.global.shared::cta.bulk_group [%0], [%1], %2;"
        :: "l"(gdst), "r"(saddr), "n"(TILE_BYTES)
        : "memory");
    asm volatile("cp.async.bulk.commit_group;" ::: "memory");
}

__global__ __launch_bounds__(BLK, 12)
void cov3d_kernel(const float* __restrict__ scaling,
                  const float* __restrict__ rotation,
                  float* __restrict__ out,
                  int N)
{
    __shared__ __align__(16) float s_out[2][TILE * 9];   // 2 x 9216 B

    const int tid  = threadIdx.x;
    const int base = blockIdx.x * PTS_PER_BLK;

    if (base + PTS_PER_BLK <= N) {
        const int n0 = base + tid;          // tile 0
        const int n1 = n0 + BLK;
        const int n2 = n1 + BLK;            // tile 1
        const int n3 = n2 + BLK;

        // Front-batched loads for BOTH tiles: MLP = 16.
        float4 q0 = __ldcs(reinterpret_cast<const float4*>(rotation) + n0);
        float4 q1 = __ldcs(reinterpret_cast<const float4*>(rotation) + n1);
        float4 q2 = __ldcs(reinterpret_cast<const float4*>(rotation) + n2);
        float4 q3 = __ldcs(reinterpret_cast<const float4*>(rotation) + n3);
        float s0x = __ldcs(scaling + (size_t)n0 * 3 + 0);
        float s0y = __ldcs(scaling + (size_t)n0 * 3 + 1);
        float s0z = __ldcs(scaling + (size_t)n0 * 3 + 2);
        float s1x = __ldcs(scaling + (size_t)n1 * 3 + 0);
        float s1y = __ldcs(scaling + (size_t)n1 * 3 + 1);
        float s1z = __ldcs(scaling + (size_t)n1 * 3 + 2);
        float s2x = __ldcs(scaling + (size_t)n2 * 3 + 0);
        float s2y = __ldcs(scaling + (size_t)n2 * 3 + 1);
        float s2z = __ldcs(scaling + (size_t)n2 * 3 + 2);
        float s3x = __ldcs(scaling + (size_t)n3 * 3 + 0);
        float s3y = __ldcs(scaling + (size_t)n3 * 3 + 1);
        float s3z = __ldcs(scaling + (size_t)n3 * 3 + 2);

        // ---- Tile 0 ----
        // Stride-9 smem writes: gcd(9,32)=1 -> conflict-free.
        compute_cov(s0x, s0y, s0z, q0, s_out[0] + tid * 9);
        compute_cov(s1x, s1y, s1z, q1, s_out[0] + (tid + BLK) * 9);
        __syncthreads();
        if (tid == 0)
            issue_tma_store(out + (size_t)base * 9, s_out[0]);   // no wait

        // ---- Tile 1 (compute fully overlaps tile-0 store) ----
        compute_cov(s2x, s2y, s2z, q2, s_out[1] + tid * 9);
        compute_cov(s3x, s3y, s3z, q3, s_out[1] + (tid + BLK) * 9);
        __syncthreads();
        if (tid == 0) {
            issue_tma_store(out + (size_t)(base + TILE) * 9, s_out[1]);
            // Single drain of both groups before CTA exit (smem lifetime);
            // hidden by the other ~11 resident CTAs per SM.
            asm volatile("cp.async.bulk.wait_group.read 0;" ::: "memory");
        }
    } else {
        #pragma unroll
        for (int k = 0; k < PTS_PER_BLK / BLK; k++) {
            int n = base + tid + k * BLK;
            if (n < N) {
                float4 q = reinterpret_cast<const float4*>(rotation)[n];
                float sx = scaling[(size_t)n * 3 + 0];
                float sy = scaling[(size_t)n * 3 + 1];
                float sz = scaling[(size_t)n * 3 + 2];
                float o[9];
                compute_cov(sx, sy, sz, q, o);
                float* dst = out + (size_t)n * 9;
                #pragma unroll
                for (int i = 0; i < 9; i++) dst[i] = o[i];
            }
        }
    }
}

extern "C" void kernel_launch(void* const* d_in, const int* in_sizes, int n_in,
                              void* d_out, int out_size)
{
    const float* scaling  = (const float*)d_in[0];   // (N,3)
    const float* rotation = (const float*)d_in[1];   // (N,4)
    float* out = (float*)d_out;                      // (N,3,3)
    int N = in_sizes[0] / 3;
    int grid = (N + PTS_PER_BLK - 1) / PTS_PER_BLK;
    cov3d_kernel<<<grid, BLK>>>(scaling, rotation, out, N);
}

// round 11
// speedup vs baseline: 1.0394x; 1.0394x over previous
#include <cuda_runtime.h>
#include <cuda_bf16.h>
#include <cstdint>

#define EPS_EYE 1e-07f
#define BLK 64
#define TILE (BLK * 2)                 // 128 points per CTA (2 per thread)
#define TILE_BYTES (TILE * 9 * 4)      // 4608

__device__ __forceinline__ uint32_t smem_u32(const void* p) {
    uint32_t a;
    asm("{ .reg .u64 t; cvta.to.shared.u64 t, %1; cvt.u32.u64 %0, t; }"
        : "=r"(a) : "l"(p));
    return a;
}

__device__ __forceinline__ void compute_cov(float sx, float sy, float sz,
                                            float4 q, float* __restrict__ o)
{
    float ex = __expf(sx), ey = __expf(sy), ez = __expf(sz);
    float a = ex * ex, b = ey * ey, c = ez * ez;

    float x = q.x, y = q.y, z = q.z, w = q.w;
    float inv = rsqrtf(x * x + y * y + z * z + w * w);
    x *= inv; y *= inv; z *= inv; w *= inv;

    float xx = x * x, yy = y * y, zz = z * z;
    float xy = x * y, xz = x * z, yz = y * z;
    float wx = w * x, wy = w * y, wz = w * z;

    float r00 = 1.f - 2.f * (yy + zz);
    float r01 = 2.f * (xy - wz);
    float r02 = 2.f * (xz + wy);
    float r10 = 2.f * (xy + wz);
    float r11 = 1.f - 2.f * (xx + zz);
    float r12 = 2.f * (yz - wx);
    float r20 = 2.f * (xz - wy);
    float r21 = 2.f * (yz + wx);
    float r22 = 1.f - 2.f * (xx + yy);

    float c00 = r00 * r00 * a + r01 * r01 * b + r02 * r02 * c + EPS_EYE;
    float c01 = r00 * r10 * a + r01 * r11 * b + r02 * r12 * c;
    float c02 = r00 * r20 * a + r01 * r21 * b + r02 * r22 * c;
    float c11 = r10 * r10 * a + r11 * r11 * b + r12 * r12 * c + EPS_EYE;
    float c12 = r10 * r20 * a + r11 * r21 * b + r12 * r22 * c;
    float c22 = r20 * r20 * a + r21 * r21 * b + r22 * r22 * c + EPS_EYE;

    o[0] = c00; o[1] = c01; o[2] = c02;
    o[3] = c01; o[4] = c11; o[5] = c12;
    o[6] = c02; o[7] = c12; o[8] = c22;
}

__global__ __launch_bounds__(BLK, 32)
void cov3d_kernel(const float* __restrict__ scaling,
                  const float* __restrict__ rotation,
                  float* __restrict__ out,
                  int N)
{
    __shared__ __align__(16) float s_out[TILE * 9];   // 4608 B

    const int tid  = threadIdx.x;
    const int base = blockIdx.x * TILE;
    const bool full = (base + TILE) <= N;

    if (full) {
        const int n0 = base + tid;
        const int n1 = n0 + BLK;

        // Front-batched loads: MLP = 8 per thread.
        float4 q0 = __ldcs(reinterpret_cast<const float4*>(rotation) + n0);
        float4 q1 = __ldcs(reinterpret_cast<const float4*>(rotation) + n1);
        float s0x = __ldcs(scaling + (size_t)n0 * 3 + 0);
        float s0y = __ldcs(scaling + (size_t)n0 * 3 + 1);
        float s0z = __ldcs(scaling + (size_t)n0 * 3 + 2);
        float s1x = __ldcs(scaling + (size_t)n1 * 3 + 0);
        float s1y = __ldcs(scaling + (size_t)n1 * 3 + 1);
        float s1z = __ldcs(scaling + (size_t)n1 * 3 + 2);

        // Stride-9 smem writes: gcd(9,32)=1 -> conflict-free.
        compute_cov(s0x, s0y, s0z, q0, s_out + tid * 9);
        compute_cov(s1x, s1y, s1z, q1, s_out + (tid + BLK) * 9);

        __syncthreads();   // 2-warp barrier: near-free

        // Single TMA bulk store: smem tile -> gmem, 36 full 128B bursts.
        if (tid == 0) {
            asm volatile("fence.proxy.async.shared::cta;" ::: "memory");
            uint32_t saddr = smem_u32(s_out);
            const float* gdst = out + (size_t)base * 9;
            asm volatile(
                "cp.async.bulk.global.shared::cta.bulk_group [%0], [%1], %2;"
                :: "l"(gdst), "r"(saddr), "n"(TILE_BYTES)
                : "memory");
            asm volatile("cp.async.bulk.commit_group;" ::: "memory");
            // Drain before CTA exit (smem lifetime); hidden by the other
            // ~31 resident CTAs per SM.
            asm volatile("cp.async.bulk.wait_group.read 0;" ::: "memory");
        }
    } else {
        #pragma unroll
        for (int k = 0; k < 2; k++) {
            int n = base + tid + k * BLK;
            if (n < N) {
                float4 q = reinterpret_cast<const float4*>(rotation)[n];
                float sx = scaling[(size_t)n * 3 + 0];
                float sy = scaling[(size_t)n * 3 + 1];
                float sz = scaling[(size_t)n * 3 + 2];
                float o[9];
                compute_cov(sx, sy, sz, q, o);
                float* dst = out + (size_t)n * 9;
                #pragma unroll
                for (int i = 0; i < 9; i++) dst[i] = o[i];
            }
        }
    }
}

extern "C" void kernel_launch(void* const* d_in, const int* in_sizes, int n_in,
                              void* d_out, int out_size)
{
    const float* scaling  = (const float*)d_in[0];   // (N,3)
    const float* rotation = (const float*)d_in[1];   // (N,4)
    float* out = (float*)d_out;                      // (N,3,3)
    int N = in_sizes[0] / 3;
    int grid = (N + TILE - 1) / TILE;
    cov3d_kernel<<<grid, BLK>>>(scaling, rotation, out, N);
}

// round 12
// speedup vs baseline: 1.0452x; 1.0056x over previous
#include <cuda_runtime.h>
#include <cuda_bf16.h>
#include <cstdint>

#define EPS_EYE 1e-07f
#define BLK 96
#define TILE (BLK * 2)                 // 192 points per CTA (2 per thread)
#define TILE_BYTES (TILE * 9 * 4)      // 6912

__device__ __forceinline__ uint32_t smem_u32(const void* p) {
    uint32_t a;
    asm("{ .reg .u64 t; cvta.to.shared.u64 t, %1; cvt.u32.u64 %0, t; }"
        : "=r"(a) : "l"(p));
    return a;
}

__device__ __forceinline__ void compute_cov(float sx, float sy, float sz,
                                            float4 q, float* __restrict__ o)
{
    float ex = __expf(sx), ey = __expf(sy), ez = __expf(sz);
    float a = ex * ex, b = ey * ey, c = ez * ez;

    float x = q.x, y = q.y, z = q.z, w = q.w;
    float inv = rsqrtf(x * x + y * y + z * z + w * w);
    x *= inv; y *= inv; z *= inv; w *= inv;

    float xx = x * x, yy = y * y, zz = z * z;
    float xy = x * y, xz = x * z, yz = y * z;
    float wx = w * x, wy = w * y, wz = w * z;

    float r00 = 1.f - 2.f * (yy + zz);
    float r01 = 2.f * (xy - wz);
    float r02 = 2.f * (xz + wy);
    float r10 = 2.f * (xy + wz);
    float r11 = 1.f - 2.f * (xx + zz);
    float r12 = 2.f * (yz - wx);
    float r20 = 2.f * (xz - wy);
    float r21 = 2.f * (yz + wx);
    float r22 = 1.f - 2.f * (xx + yy);

    float c00 = r00 * r00 * a + r01 * r01 * b + r02 * r02 * c + EPS_EYE;
    float c01 = r00 * r10 * a + r01 * r11 * b + r02 * r12 * c;
    float c02 = r00 * r20 * a + r01 * r21 * b + r02 * r22 * c;
    float c11 = r10 * r10 * a + r11 * r11 * b + r12 * r12 * c + EPS_EYE;
    float c12 = r10 * r20 * a + r11 * r21 * b + r12 * r22 * c;
    float c22 = r20 * r20 * a + r21 * r21 * b + r22 * r22 * c + EPS_EYE;

    o[0] = c00; o[1] = c01; o[2] = c02;
    o[3] = c01; o[4] = c11; o[5] = c12;
    o[6] = c02; o[7] = c12; o[8] = c22;
}

__global__ __launch_bounds__(BLK, 21)
void cov3d_kernel(const float* __restrict__ scaling,
                  const float* __restrict__ rotation,
                  float* __restrict__ out,
                  int N)
{
    __shared__ __align__(16) float s_out[TILE * 9];   // 6912 B

    const int tid  = threadIdx.x;
    const int base = blockIdx.x * TILE;
    const bool full = (base + TILE) <= N;

    if (full) {
        const int n0 = base + tid;
        const int n1 = n0 + BLK;

        // Front-batched loads: MLP = 8 per thread.
        float4 q0 = __ldcs(reinterpret_cast<const float4*>(rotation) + n0);
        float4 q1 = __ldcs(reinterpret_cast<const float4*>(rotation) + n1);
        float s0x = __ldcs(scaling + (size_t)n0 * 3 + 0);
        float s0y = __ldcs(scaling + (size_t)n0 * 3 + 1);
        float s0z = __ldcs(scaling + (size_t)n0 * 3 + 2);
        float s1x = __ldcs(scaling + (size_t)n1 * 3 + 0);
        float s1y = __ldcs(scaling + (size_t)n1 * 3 + 1);
        float s1z = __ldcs(scaling + (size_t)n1 * 3 + 2);

        // Stride-9 smem writes: gcd(9,32)=1 -> conflict-free.
        compute_cov(s0x, s0y, s0z, q0, s_out + tid * 9);
        compute_cov(s1x, s1y, s1z, q1, s_out + (tid + BLK) * 9);

        __syncthreads();   // 3-warp barrier: near-free

        // Single TMA bulk store: smem tile -> gmem, 54 full 128B bursts.
        if (tid == 0) {
            asm volatile("fence.proxy.async.shared::cta;" ::: "memory");
            uint32_t saddr = smem_u32(s_out);
            const float* gdst = out + (size_t)base * 9;
            asm volatile(
                "cp.async.bulk.global.shared::cta.bulk_group [%0], [%1], %2;"
                :: "l"(gdst), "r"(saddr), "n"(TILE_BYTES)
                : "memory");
            asm volatile("cp.async.bulk.commit_group;" ::: "memory");
            // Drain before CTA exit (smem lifetime); hidden by the other
            // ~20 resident CTAs per SM.
            asm volatile("cp.async.bulk.wait_group.read 0;" ::: "memory");
        }
    } else {
        #pragma unroll
        for (int k = 0; k < 2; k++) {
            int n = base + tid + k * BLK;
            if (n < N) {
                float4 q = reinterpret_cast<const float4*>(rotation)[n];
                float sx = scaling[(size_t)n * 3 + 0];
                float sy = scaling[(size_t)n * 3 + 1];
                float sz = scaling[(size_t)n * 3 + 2];
                float o[9];
                compute_cov(sx, sy, sz, q, o);
                float* dst = out + (size_t)n * 9;
                #pragma unroll
                for (int i = 0; i < 9; i++) dst[i] = o[i];
            }
        }
    }
}

extern "C" void kernel_launch(void* const* d_in, const int* in_sizes, int n_in,
                              void* d_out, int out_size)
{
    const float* scaling  = (const float*)d_in[0];   // (N,3)
    const float* rotation = (const float*)d_in[1];   // (N,4)
    float* out = (float*)d_out;                      // (N,3,3)
    int N = in_sizes[0] / 3;
    int grid = (N + TILE - 1) / TILE;
    cov3d_kernel<<<grid, BLK>>>(scaling, rotation, out, N);
}